// round 10
// baseline (speedup 1.0000x reference)
#include <cuda_runtime.h>
#include <cuda_bf16.h>

#define NN 100000
#define EE 1600000
#define NT 391            // node tiles of 256

#define FMA_F32X2(d, a, b, c) \
    asm("fma.rn.f32x2 %0, %1, %2, %3;" : "=l"(d) : "l"(a), "l"(b), "l"(c))
#define PACK_DUP_F32X2(out, f) do { \
    unsigned _u = __float_as_uint(f); \
    asm("mov.b64 %0, {%1, %1};" : "=l"(out) : "r"(_u)); } while (0)
#define UNPACK_F32X2(lo, hi, in) \
    asm("mov.b64 {%0, %1}, %2;" : "=f"(lo), "=f"(hi) : "l"(in))

// 2 nodes x one ulonglong2 weight pair -> 4 FFMA2
#define STEP2(acc, J, w, h0, h1) do { \
    FMA_F32X2(acc[(J)],     h0, (w).x, acc[(J)]); \
    FMA_F32X2(acc[(J)+1],   h0, (w).y, acc[(J)+1]); \
    FMA_F32X2(acc[8+(J)],   h1, (w).x, acc[8+(J)]); \
    FMA_F32X2(acc[8+(J)+1], h1, (w).y, acc[8+(J)+1]); } while (0)

// ---- device scratch (no allocation) ----
__device__ __nv_bfloat16 g_kh[(size_t)NN * 64];
__device__ __nv_bfloat16 g_qh[(size_t)NN * 64];
__device__ __nv_bfloat16 g_vh[(size_t)NN * 64];

__device__ __forceinline__ unsigned pack_bf2(float a, float b) {
    __nv_bfloat162 h = __floats2bfloat162_rn(a, b);
    return *reinterpret_cast<unsigned*>(&h);
}

// ---------------- fused persistent node kernel (self-composing) ----------------
// grid=148, 512 thr, 1 block/SM. Composes At/bh/u1/c1 in-prologue (redundant per
// block, fully parallel), stages W1 once, h1 stays in smem.
__global__ __launch_bounds__(512, 1)
void node_fused(const float* __restrict__ x,
                const float* __restrict__ W1, const float* __restrict__ b1,
                const float* __restrict__ W2, const float* __restrict__ b2,
                const float* __restrict__ Wk, const float* __restrict__ bk,
                const float* __restrict__ Wq, const float* __restrict__ bq,
                const float* __restrict__ Wv, const float* __restrict__ bv,
                const float* __restrict__ Ws, const float* __restrict__ b_gate,
                const float* __restrict__ Wsc, const float* __restrict__ bsc,
                float* __restrict__ out)
{
    extern __shared__ float sm[];
    float* at  = sm;               // 12288 : composed head weights [h][l][i]
    float* w1t = at + 12288;       // 8192  : W1^T [i=128][j=64]
    float* bb  = w1t + 8192;       // 576   : b1|bh(192)|u1|b2|wsc|ul|part..c1
    float* xs  = bb + 576;         // 8224 (32*257); scratch: W2 raw (4096)
    float* hs  = xs + 8224;        // 16384 (64*256); scratch: Wh^T stride-68 (4352)

    const int tid = threadIdx.x;

    // ===== PROLOGUE: stage + compose =====
    for (int idx = tid; idx < 8192; idx += 512) {
        int j = idx >> 7, i = idx & 127;
        w1t[i * 64 + j] = W1[idx];
    }
    for (int idx = tid; idx < 4096; idx += 512) xs[idx] = W2[idx];  // W2 raw
    if (tid < 64) {
        bb[tid]       = b1[tid];
        bb[320 + tid] = b2[tid];
        bb[384 + tid] = Wsc[tid];
        float s = 0.f;   // ul[l] = sum_j wsc_j * Ws[j,l]  (coalesced over l=tid)
        for (int j = 0; j < 64; j++) s = fmaf(Wsc[j], Ws[j * 64 + tid], s);
        bb[448 + tid] = s;
    }
    __syncthreads();

    // compose At[h] = Wh · W2  (and bh[h])
    const int i0 = (tid * 8) & 63;   // 8 consecutive i per thread
    const int lo = tid >> 3;         // l index (uniform over the 8 outputs)
    #pragma unroll 1
    for (int h = 0; h < 3; h++) {
        const float* Wh = (h == 0) ? Wk : (h == 1) ? Wq : Wv;
        // stage Wh transposed, stride 68: hs[j*68+i] = Wh[i*64+j]
        for (int idx = tid; idx < 4096; idx += 512) {
            int r = idx >> 6, c = idx & 63;
            hs[c * 68 + r] = Wh[idx];
        }
        __syncthreads();
        float acc[8];
        #pragma unroll
        for (int t = 0; t < 8; t++) acc[t] = 0.f;
        for (int j = 0; j < 64; j++) {
            float wv = xs[j * 64 + lo];                       // W2[j][lo]
            const float4* wp = (const float4*)(hs + j * 68 + i0);
            float4 wa = wp[0], wb = wp[1];
            acc[0] = fmaf(wa.x, wv, acc[0]);
            acc[1] = fmaf(wa.y, wv, acc[1]);
            acc[2] = fmaf(wa.z, wv, acc[2]);
            acc[3] = fmaf(wa.w, wv, acc[3]);
            acc[4] = fmaf(wb.x, wv, acc[4]);
            acc[5] = fmaf(wb.y, wv, acc[5]);
            acc[6] = fmaf(wb.z, wv, acc[6]);
            acc[7] = fmaf(wb.w, wv, acc[7]);
        }
        float* ao = at + h * 4096 + lo * 64 + i0;
        if (h == 2) {
            #pragma unroll
            for (int t = 0; t < 8; t++) ao[t] = acc[t] * bb[384 + i0 + t];
        } else {
            #pragma unroll
            for (int t = 0; t < 8; t++) ao[t] = acc[t];
        }
        // bh[h][i] = (bh_in[i] + sum_j Wh[i][j]*b2[j]) (× wsc[i] for h==2)
        if (tid < 64) {
            const float* bh_in = (h == 0) ? bk : (h == 1) ? bq : bv;
            float s = bh_in[tid];
            for (int j = 0; j < 64; j++) s = fmaf(hs[j * 68 + tid], bb[320 + j], s);
            bb[64 + h * 64 + tid] = (h == 2) ? s * bb[384 + tid] : s;
        }
        __syncthreads();
    }

    // u1[i] = sum_l ul[l] * W2[l][i];  c1 partials
    if (tid < 64) {
        float s = 0.f;
        for (int l = 0; l < 64; l++) s = fmaf(bb[448 + l], xs[l * 64 + tid], s);
        bb[256 + tid] = s;
        bb[512 + tid] = fmaf(bb[384 + tid], b_gate[tid], bb[448 + tid] * bb[320 + tid]);
    }
    __syncthreads();
    if (tid == 0) {
        float c = bsc[0];
        for (int j = 0; j < 64; j++) c += bb[512 + j];
        bb[575] = c;
    }
    __syncthreads();
    const float c1 = bb[575];

    // ===== TILE LOOP =====
    const int fh = tid >> 7;       // 0..3
    const int np = tid & 127;      // 0..127

    for (int tile = blockIdx.x; tile < NT; tile += gridDim.x) {
        const int base = tile * 256;

        unsigned long long acc2[16];
        {
            const unsigned long long* bp = (const unsigned long long*)(bb + fh * 16);
            #pragma unroll
            for (int k = 0; k < 2; k++)
                #pragma unroll
                for (int j = 0; j < 8; j++) acc2[k * 8 + j] = bp[j];
        }

        for (int c = 0; c < 4; c++) {
            __syncthreads();
            #pragma unroll
            for (int idx = tid; idx < 2048; idx += 512) {
                int n = idx >> 3, i4 = idx & 7;
                int nn = base + n;
                float4 v = (nn < NN) ? ((const float4*)x)[(size_t)nn * 32 + c * 8 + i4]
                                     : make_float4(0.f, 0.f, 0.f, 0.f);
                xs[(i4 * 4 + 0) * 257 + n] = v.x;
                xs[(i4 * 4 + 1) * 257 + n] = v.y;
                xs[(i4 * 4 + 2) * 257 + n] = v.z;
                xs[(i4 * 4 + 3) * 257 + n] = v.w;
            }
            __syncthreads();
            const float* wbase = w1t + c * 2048 + fh * 16;
            for (int i = 0; i < 32; i++) {
                const float* xr = xs + i * 257 + np;
                unsigned long long h0, h1;
                PACK_DUP_F32X2(h0, xr[0]);
                PACK_DUP_F32X2(h1, xr[128]);
                const ulonglong2* wr = (const ulonglong2*)(wbase + i * 64);
                { ulonglong2 w = wr[0]; STEP2(acc2, 0, w, h0, h1); }
                { ulonglong2 w = wr[1]; STEP2(acc2, 2, w, h0, h1); }
                { ulonglong2 w = wr[2]; STEP2(acc2, 4, w, h0, h1); }
                { ulonglong2 w = wr[3]; STEP2(acc2, 6, w, h0, h1); }
            }
        }

        #pragma unroll
        for (int k = 0; k < 2; k++) {
            int n = np + 128 * k;
            #pragma unroll
            for (int j = 0; j < 8; j++) {
                float lof, hif;
                UNPACK_F32X2(lof, hif, acc2[k * 8 + j]);
                hs[(fh * 16 + 2 * j + 0) * 256 + n] = fmaxf(lof, 0.f);
                hs[(fh * 16 + 2 * j + 1) * 256 + n] = fmaxf(hif, 0.f);
            }
        }
        __syncthreads();

        if (fh == 0) {
            float s0 = c1, s1 = c1;
            #pragma unroll 4
            for (int l = 0; l < 64; l++) {
                float ul = bb[256 + l];
                const float* hr = hs + l * 256 + np;
                s0 = fmaf(hr[0],   ul, s0);
                s1 = fmaf(hr[128], ul, s1);
            }
            if (base + np < NN)       out[base + np]       = s0;
            if (base + np + 128 < NN) out[base + np + 128] = s1;
        }

        #pragma unroll 1
        for (int h = 0; h < 3; h++) {
            unsigned long long a2[16];
            {
                const unsigned long long* hp =
                    (const unsigned long long*)(bb + 64 + h * 64 + fh * 16);
                #pragma unroll
                for (int k = 0; k < 2; k++)
                    #pragma unroll
                    for (int j = 0; j < 8; j++) a2[k * 8 + j] = hp[j];
            }
            const float* ah = at + h * 4096 + fh * 16;
            for (int l = 0; l < 64; l++) {
                const float* hr = hs + l * 256 + np;
                unsigned long long h0, h1;
                PACK_DUP_F32X2(h0, hr[0]);
                PACK_DUP_F32X2(h1, hr[128]);
                const ulonglong2* wr = (const ulonglong2*)(ah + l * 64);
                { ulonglong2 w = wr[0]; STEP2(a2, 0, w, h0, h1); }
                { ulonglong2 w = wr[1]; STEP2(a2, 2, w, h0, h1); }
                { ulonglong2 w = wr[2]; STEP2(a2, 4, w, h0, h1); }
                { ulonglong2 w = wr[3]; STEP2(a2, 6, w, h0, h1); }
            }
            __nv_bfloat16* dp = (h == 0) ? g_kh : (h == 1) ? g_qh : g_vh;
            #pragma unroll
            for (int k = 0; k < 2; k++) {
                int node = base + np + 128 * k;
                if (node < NN) {
                    uint4 u;
                    float a0, a1, b0, b1, c0, c0b, d0, d1;
                    UNPACK_F32X2(a0, a1, a2[k * 8 + 0]);
                    UNPACK_F32X2(b0, b1, a2[k * 8 + 1]);
                    UNPACK_F32X2(c0, c0b, a2[k * 8 + 2]);
                    UNPACK_F32X2(d0, d1, a2[k * 8 + 3]);
                    u.x = pack_bf2(a0, a1); u.y = pack_bf2(b0, b1);
                    u.z = pack_bf2(c0, c0b); u.w = pack_bf2(d0, d1);
                    *(uint4*)(dp + (size_t)node * 64 + fh * 16) = u;
                    UNPACK_F32X2(a0, a1, a2[k * 8 + 4]);
                    UNPACK_F32X2(b0, b1, a2[k * 8 + 5]);
                    UNPACK_F32X2(c0, c0b, a2[k * 8 + 6]);
                    UNPACK_F32X2(d0, d1, a2[k * 8 + 7]);
                    u.x = pack_bf2(a0, a1); u.y = pack_bf2(b0, b1);
                    u.z = pack_bf2(c0, c0b); u.w = pack_bf2(d0, d1);
                    *(uint4*)(dp + (size_t)node * 64 + fh * 16 + 8) = u;
                }
            }
        }
    }
}

// ---------------- edge kernel: 4 lanes/edge, bf16, 32-bit offsets ----------------
__device__ __forceinline__ float sigf(float x) {
    float t;
    asm("tanh.approx.f32 %0, %1;" : "=f"(t) : "f"(x * 0.5f));
    return fmaf(t, 0.5f, 0.5f);
}
__device__ __forceinline__ float2 bf2f(unsigned u) {
    __nv_bfloat162 h = *reinterpret_cast<__nv_bfloat162*>(&u);
    return __bfloat1622float2(h);
}
__device__ __forceinline__ float edge8(uint4 kk, uint4 qq, uint4 vv) {
    float s = 0.f;
    {
        float2 kf = bf2f(kk.x), qf = bf2f(qq.x), vf = bf2f(vv.x);
        s += sigf(kf.x + qf.x) * vf.x + sigf(kf.y + qf.y) * vf.y;
    }
    {
        float2 kf = bf2f(kk.y), qf = bf2f(qq.y), vf = bf2f(vv.y);
        s += sigf(kf.x + qf.x) * vf.x + sigf(kf.y + qf.y) * vf.y;
    }
    {
        float2 kf = bf2f(kk.z), qf = bf2f(qq.z), vf = bf2f(vv.z);
        s += sigf(kf.x + qf.x) * vf.x + sigf(kf.y + qf.y) * vf.y;
    }
    {
        float2 kf = bf2f(kk.w), qf = bf2f(qq.w), vf = bf2f(vv.w);
        s += sigf(kf.x + qf.x) * vf.x + sigf(kf.y + qf.y) * vf.y;
    }
    return s;
}

__global__ __launch_bounds__(256)
void edge_kernel(const int* __restrict__ ei, float* __restrict__ out)
{
    int t = blockIdx.x * 256 + threadIdx.x;
    int e = t >> 2;
    if (e >= EE) return;
    unsigned sub = t & 3;

    unsigned src = (unsigned)ei[e];
    unsigned dst = (unsigned)ei[EE + e];

    unsigned ko = (dst << 6) + (sub << 4);
    unsigned so = (src << 6) + (sub << 4);
    const uint4* kp = (const uint4*)(g_kh + ko);
    const uint4* qp = (const uint4*)(g_qh + so);
    const uint4* vp = (const uint4*)(g_vh + so);
    uint4 k0 = kp[0], k1 = kp[1];
    uint4 q0 = qp[0], q1 = qp[1];
    uint4 v0 = vp[0], v1 = vp[1];

    float s = edge8(k0, q0, v0) + edge8(k1, q1, v1);

    s += __shfl_down_sync(0xffffffffu, s, 2, 4);
    s += __shfl_down_sync(0xffffffffu, s, 1, 4);
    if (sub == 0) atomicAdd(out + dst, s);
}

extern "C" void kernel_launch(void* const* d_in, const int* in_sizes, int n_in,
                              void* d_out, int out_size)
{
    const float* x      = (const float*)d_in[0];
    const int*   ei     = (const int*)d_in[1];
    const float* W1     = (const float*)d_in[2];
    const float* b1     = (const float*)d_in[3];
    const float* W2     = (const float*)d_in[4];
    const float* b2     = (const float*)d_in[5];
    const float* Wk     = (const float*)d_in[6];
    const float* bk     = (const float*)d_in[7];
    const float* Wq     = (const float*)d_in[8];
    const float* bq     = (const float*)d_in[9];
    const float* Wv     = (const float*)d_in[10];
    const float* bv     = (const float*)d_in[11];
    const float* Ws     = (const float*)d_in[12];
    const float* b_gate = (const float*)d_in[13];
    const float* Wsc    = (const float*)d_in[14];
    const float* bsc    = (const float*)d_in[15];
    float* out = (float*)d_out;

    // 12288 + 8192 + 576 + 8224 + 16384 = 45664 floats = 182.7 KB
    size_t smemf = (12288 + 8192 + 576 + 8224 + 16384) * sizeof(float);
    cudaFuncSetAttribute(node_fused, cudaFuncAttributeMaxDynamicSharedMemorySize, (int)smemf);

    node_fused<<<148, 512, smemf>>>(x, W1, b1, W2, b2, Wk, bk, Wq, bq,
                                    Wv, bv, Ws, b_gate, Wsc, bsc, out);
    edge_kernel<<<(EE * 4) / 256, 256>>>(ei, out);
}

// round 11
// speedup vs baseline: 1.5229x; 1.5229x over previous
#include <cuda_runtime.h>
#include <cuda_bf16.h>

#define NN 100000
#define EE 1600000
#define NT 391            // node tiles of 256

#define FMA_F32X2(d, a, b, c) \
    asm("fma.rn.f32x2 %0, %1, %2, %3;" : "=l"(d) : "l"(a), "l"(b), "l"(c))
#define PACK_DUP_F32X2(out, f) do { \
    unsigned _u = __float_as_uint(f); \
    asm("mov.b64 %0, {%1, %1};" : "=l"(out) : "r"(_u)); } while (0)
#define UNPACK_F32X2(lo, hi, in) \
    asm("mov.b64 {%0, %1}, %2;" : "=f"(lo), "=f"(hi) : "l"(in))

// 2 nodes x one ulonglong2 weight pair -> 4 FFMA2
#define STEP2(acc, J, w, h0, h1) do { \
    FMA_F32X2(acc[(J)],     h0, (w).x, acc[(J)]); \
    FMA_F32X2(acc[(J)+1],   h0, (w).y, acc[(J)+1]); \
    FMA_F32X2(acc[8+(J)],   h1, (w).x, acc[8+(J)]); \
    FMA_F32X2(acc[8+(J)+1], h1, (w).y, acc[8+(J)+1]); } while (0)

// ---- device scratch (no allocation) ----
__device__ float g_At[3 * 64 * 64];             // composed head weights [h][l][i]
__device__ float g_bh[3 * 64];                  // composed head biases
__device__ float g_u1[64];                      // W2^T Ws^T wsc
__device__ float g_c1;
__device__ __nv_bfloat16 g_kh[(size_t)NN * 64];
__device__ __nv_bfloat16 g_qh[(size_t)NN * 64];
__device__ __nv_bfloat16 g_vh[(size_t)NN * 64];

// ---------------- prologue: compose weights (16 blocks, short chains) ----------------
__global__ __launch_bounds__(256)
void prec(const float* __restrict__ W2, const float* __restrict__ b2,
          const float* __restrict__ Wk, const float* __restrict__ bk,
          const float* __restrict__ Wq, const float* __restrict__ bq,
          const float* __restrict__ Wv, const float* __restrict__ bv,
          const float* __restrict__ Ws, const float* __restrict__ b_gate,
          const float* __restrict__ Wsc, const float* __restrict__ bsc)
{
    const int tid = threadIdx.x;
    const int blk = blockIdx.x;

    if (blk < 12) {
        // head h, l-quarter q: At[h][l][i] = sum_j Wh[i*64+j] * W2[j*64+l]
        const int h = blk >> 2, q = blk & 3;
        __shared__ float wht[65 * 64];   // Wh transposed, stride 65: wht[j*65+i]
        __shared__ float w2q[16 * 64];   // W2 quarter: w2q[j*16+ls] = W2[j*64 + q*16+ls]
        __shared__ float wscs[64];
        const float* Wh = h == 0 ? Wk : h == 1 ? Wq : Wv;
        for (int idx = tid; idx < 4096; idx += 256) {
            int r = idx >> 6, c = idx & 63;       // Wh row i=r, col j=c
            wht[c * 65 + r] = Wh[idx];
        }
        for (int idx = tid; idx < 1024; idx += 256) {
            int j = idx >> 4, ls = idx & 15;
            w2q[idx] = W2[j * 64 + q * 16 + ls];
        }
        if (tid < 64) wscs[tid] = Wsc[tid];
        __syncthreads();

        const int i = tid & 63;
        const int lsub = tid >> 6;                // 0..3 (uniform per warp)
        float acc[4] = {0.f, 0.f, 0.f, 0.f};
        for (int j = 0; j < 64; j++) {
            float wv = wht[j * 65 + i];
            acc[0] = fmaf(wv, w2q[j * 16 + lsub + 0],  acc[0]);
            acc[1] = fmaf(wv, w2q[j * 16 + lsub + 4],  acc[1]);
            acc[2] = fmaf(wv, w2q[j * 16 + lsub + 8],  acc[2]);
            acc[3] = fmaf(wv, w2q[j * 16 + lsub + 12], acc[3]);
        }
        float scale = (h == 2) ? wscs[i] : 1.f;
        #pragma unroll
        for (int t = 0; t < 4; t++) {
            int l = q * 16 + lsub + 4 * t;
            g_At[h * 4096 + l * 64 + i] = acc[t] * scale;
        }
    } else if (blk < 15) {
        // bh[h][i] = bh_in[i] + sum_j Wh[i][j]*b2[j]  (× wsc[i] for h==2)
        const int h = blk - 12;
        __shared__ float whs[65 * 64];
        __shared__ float b2s[64], wscs[64], part[256];
        const float* Wh = h == 0 ? Wk : h == 1 ? Wq : Wv;
        for (int idx = tid; idx < 4096; idx += 256) {
            int r = idx >> 6, c = idx & 63;
            whs[c * 65 + r] = Wh[idx];
        }
        if (tid < 64) { b2s[tid] = b2[tid]; wscs[tid] = Wsc[tid]; }
        __syncthreads();
        const int i = tid & 63, jg = tid >> 6;
        float s = 0.f;
        #pragma unroll
        for (int jj = 0; jj < 16; jj++) {
            int j = jg * 16 + jj;
            s = fmaf(whs[j * 65 + i], b2s[j], s);
        }
        part[jg * 64 + i] = s;
        __syncthreads();
        if (tid < 64) {
            const float* bh_in = h == 0 ? bk : h == 1 ? bq : bv;
            float v = bh_in[tid] + part[tid] + part[64 + tid] + part[128 + tid] + part[192 + tid];
            g_bh[h * 64 + tid] = (h == 2) ? v * wscs[tid] : v;
        }
    } else {
        // ul, u1, c1
        __shared__ float part[256], uls[64], csum[64];
        const int l = tid & 63, jg = tid >> 6;
        float s = 0.f;
        #pragma unroll
        for (int jj = 0; jj < 16; jj++) {
            int j = jg * 16 + jj;
            s = fmaf(Wsc[j], Ws[j * 64 + l], s);  // coalesced over l
        }
        part[jg * 64 + l] = s;
        __syncthreads();
        if (tid < 64) uls[tid] = part[tid] + part[64 + tid] + part[128 + tid] + part[192 + tid];
        __syncthreads();
        // u1[i] = sum_l ul[l] * W2[l*64+i]
        float t2 = 0.f;
        #pragma unroll
        for (int ll = 0; ll < 16; ll++) {
            int lv = jg * 16 + ll;
            t2 = fmaf(uls[lv], W2[lv * 64 + l], t2);  // coalesced over i=l
        }
        part[jg * 64 + l] = t2;
        __syncthreads();
        if (tid < 64) {
            g_u1[tid] = part[tid] + part[64 + tid] + part[128 + tid] + part[192 + tid];
            csum[tid] = fmaf(Wsc[tid], b_gate[tid], uls[tid] * b2[tid]);
        }
        __syncthreads();
        if (tid == 0) {
            float c = bsc[0];
            for (int j = 0; j < 64; j++) c += csum[j];
            g_c1 = c;
        }
    }
}

__device__ __forceinline__ unsigned pack_bf2(float a, float b) {
    __nv_bfloat162 h = __floats2bfloat162_rn(a, b);
    return *reinterpret_cast<unsigned*>(&h);
}

// ---------------- fused persistent node kernel (exact R9) ----------------
__global__ __launch_bounds__(512, 1)
void node_fused(const float* __restrict__ x,
                const float* __restrict__ W1, const float* __restrict__ b1,
                float* __restrict__ out)
{
    extern __shared__ float sm[];
    float* at  = sm;               // 12288
    float* w1t = at + 12288;       // 8192 : [i=128][j=64]
    float* bb  = w1t + 8192;       // 320 : b1(64) | bh(192) | u1(64)
    float* xs  = bb + 320;         // 32 * 257
    float* hs  = xs + 32 * 257;    // 64 * 256

    const int tid = threadIdx.x;

    for (int idx = tid; idx < 8192; idx += 512) {
        int j = idx >> 7, i = idx & 127;
        w1t[i * 64 + j] = W1[idx];
    }
    for (int idx = tid; idx < 3072; idx += 512)
        ((float4*)at)[idx] = ((const float4*)g_At)[idx];
    if (tid < 64)       bb[tid] = b1[tid];
    else if (tid < 256) bb[tid] = g_bh[tid - 64];
    else if (tid < 320) bb[tid] = g_u1[tid - 256];
    const float c1 = g_c1;
    __syncthreads();

    const int fh = tid >> 7;       // 0..3
    const int np = tid & 127;      // 0..127

    for (int tile = blockIdx.x; tile < NT; tile += gridDim.x) {
        const int base = tile * 256;

        unsigned long long acc2[16];
        {
            const unsigned long long* bp = (const unsigned long long*)(bb + fh * 16);
            #pragma unroll
            for (int k = 0; k < 2; k++)
                #pragma unroll
                for (int j = 0; j < 8; j++) acc2[k * 8 + j] = bp[j];
        }

        for (int c = 0; c < 4; c++) {
            __syncthreads();
            #pragma unroll
            for (int idx = tid; idx < 2048; idx += 512) {
                int n = idx >> 3, i4 = idx & 7;
                int nn = base + n;
                float4 v = (nn < NN) ? ((const float4*)x)[(size_t)nn * 32 + c * 8 + i4]
                                     : make_float4(0.f, 0.f, 0.f, 0.f);
                xs[(i4 * 4 + 0) * 257 + n] = v.x;
                xs[(i4 * 4 + 1) * 257 + n] = v.y;
                xs[(i4 * 4 + 2) * 257 + n] = v.z;
                xs[(i4 * 4 + 3) * 257 + n] = v.w;
            }
            __syncthreads();
            const float* wbase = w1t + c * 2048 + fh * 16;
            for (int i = 0; i < 32; i++) {
                const float* xr = xs + i * 257 + np;
                unsigned long long h0, h1;
                PACK_DUP_F32X2(h0, xr[0]);
                PACK_DUP_F32X2(h1, xr[128]);
                const ulonglong2* wr = (const ulonglong2*)(wbase + i * 64);
                { ulonglong2 w = wr[0]; STEP2(acc2, 0, w, h0, h1); }
                { ulonglong2 w = wr[1]; STEP2(acc2, 2, w, h0, h1); }
                { ulonglong2 w = wr[2]; STEP2(acc2, 4, w, h0, h1); }
                { ulonglong2 w = wr[3]; STEP2(acc2, 6, w, h0, h1); }
            }
        }

        #pragma unroll
        for (int k = 0; k < 2; k++) {
            int n = np + 128 * k;
            #pragma unroll
            for (int j = 0; j < 8; j++) {
                float lof, hif;
                UNPACK_F32X2(lof, hif, acc2[k * 8 + j]);
                hs[(fh * 16 + 2 * j + 0) * 256 + n] = fmaxf(lof, 0.f);
                hs[(fh * 16 + 2 * j + 1) * 256 + n] = fmaxf(hif, 0.f);
            }
        }
        __syncthreads();

        if (fh == 0) {
            float s0 = c1, s1 = c1;
            #pragma unroll 4
            for (int l = 0; l < 64; l++) {
                float ul = bb[256 + l];
                const float* hr = hs + l * 256 + np;
                s0 = fmaf(hr[0],   ul, s0);
                s1 = fmaf(hr[128], ul, s1);
            }
            if (base + np < NN)       out[base + np]       = s0;
            if (base + np + 128 < NN) out[base + np + 128] = s1;
        }

        #pragma unroll 1
        for (int h = 0; h < 3; h++) {
            unsigned long long a2[16];
            {
                const unsigned long long* hp =
                    (const unsigned long long*)(bb + 64 + h * 64 + fh * 16);
                #pragma unroll
                for (int k = 0; k < 2; k++)
                    #pragma unroll
                    for (int j = 0; j < 8; j++) a2[k * 8 + j] = hp[j];
            }
            const float* ah = at + h * 4096 + fh * 16;
            for (int l = 0; l < 64; l++) {
                const float* hr = hs + l * 256 + np;
                unsigned long long h0, h1;
                PACK_DUP_F32X2(h0, hr[0]);
                PACK_DUP_F32X2(h1, hr[128]);
                const ulonglong2* wr = (const ulonglong2*)(ah + l * 64);
                { ulonglong2 w = wr[0]; STEP2(a2, 0, w, h0, h1); }
                { ulonglong2 w = wr[1]; STEP2(a2, 2, w, h0, h1); }
                { ulonglong2 w = wr[2]; STEP2(a2, 4, w, h0, h1); }
                { ulonglong2 w = wr[3]; STEP2(a2, 6, w, h0, h1); }
            }
            __nv_bfloat16* dp = (h == 0) ? g_kh : (h == 1) ? g_qh : g_vh;
            #pragma unroll
            for (int k = 0; k < 2; k++) {
                int node = base + np + 128 * k;
                if (node < NN) {
                    uint4 u;
                    float a0, a1, b0, b1, c0, c0b, d0, d1;
                    UNPACK_F32X2(a0, a1, a2[k * 8 + 0]);
                    UNPACK_F32X2(b0, b1, a2[k * 8 + 1]);
                    UNPACK_F32X2(c0, c0b, a2[k * 8 + 2]);
                    UNPACK_F32X2(d0, d1, a2[k * 8 + 3]);
                    u.x = pack_bf2(a0, a1); u.y = pack_bf2(b0, b1);
                    u.z = pack_bf2(c0, c0b); u.w = pack_bf2(d0, d1);
                    *(uint4*)(dp + (size_t)node * 64 + fh * 16) = u;
                    UNPACK_F32X2(a0, a1, a2[k * 8 + 4]);
                    UNPACK_F32X2(b0, b1, a2[k * 8 + 5]);
                    UNPACK_F32X2(c0, c0b, a2[k * 8 + 6]);
                    UNPACK_F32X2(d0, d1, a2[k * 8 + 7]);
                    u.x = pack_bf2(a0, a1); u.y = pack_bf2(b0, b1);
                    u.z = pack_bf2(c0, c0b); u.w = pack_bf2(d0, d1);
                    *(uint4*)(dp + (size_t)node * 64 + fh * 16 + 8) = u;
                }
            }
        }
    }
}

// ---------------- edge kernel: 4 lanes/edge, bf16 (exact R9/R6, 50us) ----------------
__device__ __forceinline__ float sigf(float x) {
    float t;
    asm("tanh.approx.f32 %0, %1;" : "=f"(t) : "f"(x * 0.5f));
    return fmaf(t, 0.5f, 0.5f);
}
__device__ __forceinline__ float2 bf2f(unsigned u) {
    __nv_bfloat162 h = *reinterpret_cast<__nv_bfloat162*>(&u);
    return __bfloat1622float2(h);
}
__device__ __forceinline__ float edge8(uint4 kk, uint4 qq, uint4 vv) {
    float s = 0.f;
    {
        float2 kf = bf2f(kk.x), qf = bf2f(qq.x), vf = bf2f(vv.x);
        s += sigf(kf.x + qf.x) * vf.x + sigf(kf.y + qf.y) * vf.y;
    }
    {
        float2 kf = bf2f(kk.y), qf = bf2f(qq.y), vf = bf2f(vv.y);
        s += sigf(kf.x + qf.x) * vf.x + sigf(kf.y + qf.y) * vf.y;
    }
    {
        float2 kf = bf2f(kk.z), qf = bf2f(qq.z), vf = bf2f(vv.z);
        s += sigf(kf.x + qf.x) * vf.x + sigf(kf.y + qf.y) * vf.y;
    }
    {
        float2 kf = bf2f(kk.w), qf = bf2f(qq.w), vf = bf2f(vv.w);
        s += sigf(kf.x + qf.x) * vf.x + sigf(kf.y + qf.y) * vf.y;
    }
    return s;
}

__global__ __launch_bounds__(256)
void edge_kernel(const int* __restrict__ ei, float* __restrict__ out)
{
    int t = blockIdx.x * 256 + threadIdx.x;
    int e = t >> 2;
    if (e >= EE) return;
    int sub = t & 3;

    int src = ei[e];
    int dst = ei[EE + e];

    const uint4* kp = (const uint4*)(g_kh + (size_t)dst * 64 + sub * 16);
    const uint4* qp = (const uint4*)(g_qh + (size_t)src * 64 + sub * 16);
    const uint4* vp = (const uint4*)(g_vh + (size_t)src * 64 + sub * 16);
    uint4 k0 = kp[0], k1 = kp[1];
    uint4 q0 = qp[0], q1 = qp[1];
    uint4 v0 = vp[0], v1 = vp[1];

    float s = edge8(k0, q0, v0) + edge8(k1, q1, v1);

    s += __shfl_down_sync(0xffffffffu, s, 2, 4);
    s += __shfl_down_sync(0xffffffffu, s, 1, 4);
    if (sub == 0) atomicAdd(out + dst, s);
}

extern "C" void kernel_launch(void* const* d_in, const int* in_sizes, int n_in,
                              void* d_out, int out_size)
{
    const float* x      = (const float*)d_in[0];
    const int*   ei     = (const int*)d_in[1];
    const float* W1     = (const float*)d_in[2];
    const float* b1     = (const float*)d_in[3];
    const float* W2     = (const float*)d_in[4];
    const float* b2     = (const float*)d_in[5];
    const float* Wk     = (const float*)d_in[6];
    const float* bk     = (const float*)d_in[7];
    const float* Wq     = (const float*)d_in[8];
    const float* bq     = (const float*)d_in[9];
    const float* Wv     = (const float*)d_in[10];
    const float* bv     = (const float*)d_in[11];
    const float* Ws     = (const float*)d_in[12];
    const float* b_gate = (const float*)d_in[13];
    const float* Wsc    = (const float*)d_in[14];
    const float* bsc    = (const float*)d_in[15];
    float* out = (float*)d_out;

    size_t smemf = (12288 + 8192 + 320 + 32 * 257 + 64 * 256) * sizeof(float);  // ~177.4 KB
    cudaFuncSetAttribute(node_fused, cudaFuncAttributeMaxDynamicSharedMemorySize, (int)smemf);

    prec<<<16, 256>>>(W2, b2, Wk, bk, Wq, bq, Wv, bv, Ws, b_gate, Wsc, bsc);
    node_fused<<<148, 512, smemf>>>(x, W1, b1, out);
    edge_kernel<<<(EE * 4) / 256, 256>>>(ei, out);
}

// round 12
// speedup vs baseline: 1.8926x; 1.2427x over previous
#include <cuda_runtime.h>
#include <cuda_bf16.h>

#define NN 100000
#define EE 1600000
#define NT 391            // node tiles of 256

#define FMA_F32X2(d, a, b, c) \
    asm("fma.rn.f32x2 %0, %1, %2, %3;" : "=l"(d) : "l"(a), "l"(b), "l"(c))
#define PACK_DUP_F32X2(out, f) do { \
    unsigned _u = __float_as_uint(f); \
    asm("mov.b64 %0, {%1, %1};" : "=l"(out) : "r"(_u)); } while (0)
#define UNPACK_F32X2(lo, hi, in) \
    asm("mov.b64 {%0, %1}, %2;" : "=f"(lo), "=f"(hi) : "l"(in))

#define STEP2(acc, J, w, h0, h1) do { \
    FMA_F32X2(acc[(J)],     h0, (w).x, acc[(J)]); \
    FMA_F32X2(acc[(J)+1],   h0, (w).y, acc[(J)+1]); \
    FMA_F32X2(acc[8+(J)],   h1, (w).x, acc[8+(J)]); \
    FMA_F32X2(acc[8+(J)+1], h1, (w).y, acc[8+(J)+1]); } while (0)

#define MMA_TF32(d0,d1,d2,d3,a0,a1,a2,a3,b0,b1) \
    asm("mma.sync.aligned.m16n8k8.row.col.f32.tf32.tf32.f32 " \
        "{%0,%1,%2,%3},{%4,%5,%6,%7},{%8,%9},{%0,%1,%2,%3};" \
        : "+f"(d0), "+f"(d1), "+f"(d2), "+f"(d3) \
        : "r"(a0), "r"(a1), "r"(a2), "r"(a3), "r"(b0), "r"(b1))

__device__ __forceinline__ unsigned cvt_tf32(float f) {
    unsigned u;
    asm("cvt.rna.tf32.f32 %0, %1;" : "=r"(u) : "f"(f));
    return u;
}

// ---- device scratch (no allocation) ----
__device__ float g_Atb2[64 * 192];              // composed head weights, tf32 bits, [l][h*64+i]
__device__ float g_bh[3 * 64];                  // composed head biases (fp32)
__device__ float g_u1[64];                      // W2^T Ws^T wsc
__device__ float g_c1;
__device__ __nv_bfloat16 g_kh[(size_t)NN * 64];
__device__ __nv_bfloat16 g_qh[(size_t)NN * 64];
__device__ __nv_bfloat16 g_vh[(size_t)NN * 64];

// ---------------- prologue: compose weights (16 blocks, short chains) ----------------
__global__ __launch_bounds__(256)
void prec(const float* __restrict__ W2, const float* __restrict__ b2,
          const float* __restrict__ Wk, const float* __restrict__ bk,
          const float* __restrict__ Wq, const float* __restrict__ bq,
          const float* __restrict__ Wv, const float* __restrict__ bv,
          const float* __restrict__ Ws, const float* __restrict__ b_gate,
          const float* __restrict__ Wsc, const float* __restrict__ bsc)
{
    const int tid = threadIdx.x;
    const int blk = blockIdx.x;

    if (blk < 12) {
        // head h, l-quarter q: At[l][i] = sum_j Wh[i*64+j] * W2[j*64+l]
        const int h = blk >> 2, q = blk & 3;
        __shared__ float wht[65 * 64];   // Wh transposed, stride 65
        __shared__ float w2q[16 * 64];
        __shared__ float wscs[64];
        const float* Wh = h == 0 ? Wk : h == 1 ? Wq : Wv;
        for (int idx = tid; idx < 4096; idx += 256) {
            int r = idx >> 6, c = idx & 63;
            wht[c * 65 + r] = Wh[idx];
        }
        for (int idx = tid; idx < 1024; idx += 256) {
            int j = idx >> 4, ls = idx & 15;
            w2q[idx] = W2[j * 64 + q * 16 + ls];
        }
        if (tid < 64) wscs[tid] = Wsc[tid];
        __syncthreads();

        const int i = tid & 63;
        const int lsub = tid >> 6;
        float acc[4] = {0.f, 0.f, 0.f, 0.f};
        for (int j = 0; j < 64; j++) {
            float wv = wht[j * 65 + i];
            acc[0] = fmaf(wv, w2q[j * 16 + lsub + 0],  acc[0]);
            acc[1] = fmaf(wv, w2q[j * 16 + lsub + 4],  acc[1]);
            acc[2] = fmaf(wv, w2q[j * 16 + lsub + 8],  acc[2]);
            acc[3] = fmaf(wv, w2q[j * 16 + lsub + 12], acc[3]);
        }
        float scale = (h == 2) ? wscs[i] : 1.f;
        #pragma unroll
        for (int t = 0; t < 4; t++) {
            int l = q * 16 + lsub + 4 * t;
            g_Atb2[l * 192 + h * 64 + i] = __uint_as_float(cvt_tf32(acc[t] * scale));
        }
    } else if (blk < 15) {
        const int h = blk - 12;
        __shared__ float whs[65 * 64];
        __shared__ float b2s[64], wscs[64], part[256];
        const float* Wh = h == 0 ? Wk : h == 1 ? Wq : Wv;
        for (int idx = tid; idx < 4096; idx += 256) {
            int r = idx >> 6, c = idx & 63;
            whs[c * 65 + r] = Wh[idx];
        }
        if (tid < 64) { b2s[tid] = b2[tid]; wscs[tid] = Wsc[tid]; }
        __syncthreads();
        const int i = tid & 63, jg = tid >> 6;
        float s = 0.f;
        #pragma unroll
        for (int jj = 0; jj < 16; jj++) {
            int j = jg * 16 + jj;
            s = fmaf(whs[j * 65 + i], b2s[j], s);
        }
        part[jg * 64 + i] = s;
        __syncthreads();
        if (tid < 64) {
            const float* bh_in = h == 0 ? bk : h == 1 ? bq : bv;
            float v = bh_in[tid] + part[tid] + part[64 + tid] + part[128 + tid] + part[192 + tid];
            g_bh[h * 64 + tid] = (h == 2) ? v * wscs[tid] : v;
        }
    } else {
        __shared__ float part[256], uls[64], csum[64];
        const int l = tid & 63, jg = tid >> 6;
        float s = 0.f;
        #pragma unroll
        for (int jj = 0; jj < 16; jj++) {
            int j = jg * 16 + jj;
            s = fmaf(Wsc[j], Ws[j * 64 + l], s);
        }
        part[jg * 64 + l] = s;
        __syncthreads();
        if (tid < 64) uls[tid] = part[tid] + part[64 + tid] + part[128 + tid] + part[192 + tid];
        __syncthreads();
        float t2 = 0.f;
        #pragma unroll
        for (int ll = 0; ll < 16; ll++) {
            int lv = jg * 16 + ll;
            t2 = fmaf(uls[lv], W2[lv * 64 + l], t2);
        }
        part[jg * 64 + l] = t2;
        __syncthreads();
        if (tid < 64) {
            g_u1[tid] = part[tid] + part[64 + tid] + part[128 + tid] + part[192 + tid];
            csum[tid] = fmaf(Wsc[tid], b_gate[tid], uls[tid] * b2[tid]);
        }
        __syncthreads();
        if (tid == 0) {
            float c = bsc[0];
            for (int j = 0; j < 64; j++) c += csum[j];
            g_c1 = c;
        }
    }
}

__device__ __forceinline__ unsigned pack_bf2(float a, float b) {
    __nv_bfloat162 h = __floats2bfloat162_rn(a, b);
    return *reinterpret_cast<unsigned*>(&h);
}

// ---------------- fused persistent node kernel: fp32 layer1 + tf32 mma heads ----------------
__global__ __launch_bounds__(512, 1)
void node_fused(const float* __restrict__ x,
                const float* __restrict__ W1, const float* __restrict__ b1,
                float* __restrict__ out)
{
    extern __shared__ float sm[];
    float* w1t  = sm;                // 8192 : W1^T [i=128][j=64]
    float* bb   = w1t + 8192;        // 320  : b1(64) | u1(64) | bh(192)
    float* psc  = bb + 320;          // 1024 : score partials [4][256]
    float* xs   = psc + 1024;        // 8224 : 32*257 x staging
    float* hsf  = xs + 8224;         // 16640: h1 tf32 [node=256][stride 65]
    float* atb2 = hsf + 16640;       // 12800: At tf32 [l=64][stride 200]

    const int tid = threadIdx.x;

    for (int idx = tid; idx < 8192; idx += 512) {
        int j = idx >> 7, i = idx & 127;
        w1t[i * 64 + j] = W1[idx];
    }
    for (int idx = tid; idx < 12288; idx += 512)
        atb2[(idx / 192) * 200 + idx % 192] = g_Atb2[idx];
    if (tid < 64) {
        bb[tid]      = b1[tid];
        bb[64 + tid] = g_u1[tid];
    }
    if (tid < 192) bb[128 + tid] = g_bh[tid];
    const float c1 = g_c1;
    __syncthreads();

    const int fh = tid >> 7;       // 0..3
    const int np = tid & 127;      // 0..127
    const int tw = tid >> 5;       // warp 0..15
    const int lane = tid & 31;

    for (int tile = blockIdx.x; tile < NT; tile += gridDim.x) {
        const int base = tile * 256;

        // ---- layer 1 (fp32 f32x2) ----
        unsigned long long acc2[16];
        {
            const unsigned long long* bp = (const unsigned long long*)(bb + fh * 16);
            #pragma unroll
            for (int k = 0; k < 2; k++)
                #pragma unroll
                for (int j = 0; j < 8; j++) acc2[k * 8 + j] = bp[j];
        }

        for (int c = 0; c < 4; c++) {
            __syncthreads();
            #pragma unroll
            for (int idx = tid; idx < 2048; idx += 512) {
                int n = idx >> 3, i4 = idx & 7;
                int nn = base + n;
                float4 v = (nn < NN) ? ((const float4*)x)[(size_t)nn * 32 + c * 8 + i4]
                                     : make_float4(0.f, 0.f, 0.f, 0.f);
                xs[(i4 * 4 + 0) * 257 + n] = v.x;
                xs[(i4 * 4 + 1) * 257 + n] = v.y;
                xs[(i4 * 4 + 2) * 257 + n] = v.z;
                xs[(i4 * 4 + 3) * 257 + n] = v.w;
            }
            __syncthreads();
            const float* wbase = w1t + c * 2048 + fh * 16;
            for (int i = 0; i < 32; i++) {
                const float* xr = xs + i * 257 + np;
                unsigned long long h0, h1;
                PACK_DUP_F32X2(h0, xr[0]);
                PACK_DUP_F32X2(h1, xr[128]);
                const ulonglong2* wr = (const ulonglong2*)(wbase + i * 64);
                { ulonglong2 w = wr[0]; STEP2(acc2, 0, w, h0, h1); }
                { ulonglong2 w = wr[1]; STEP2(acc2, 2, w, h0, h1); }
                { ulonglong2 w = wr[2]; STEP2(acc2, 4, w, h0, h1); }
                { ulonglong2 w = wr[3]; STEP2(acc2, 6, w, h0, h1); }
            }
        }

        // ---- epilogue: relu, score partials (fp32), h1 -> smem tf32 ----
        {
            float sp0 = 0.f, sp1 = 0.f;
            #pragma unroll
            for (int k = 0; k < 2; k++) {
                int n = np + 128 * k;
                float* hrow = hsf + n * 65 + fh * 16;
                #pragma unroll
                for (int j = 0; j < 8; j++) {
                    float lo, hi;
                    UNPACK_F32X2(lo, hi, acc2[k * 8 + j]);
                    lo = fmaxf(lo, 0.f);
                    hi = fmaxf(hi, 0.f);
                    float u0 = bb[64 + fh * 16 + 2 * j];
                    float u1v = bb[64 + fh * 16 + 2 * j + 1];
                    if (k == 0) sp0 = fmaf(lo, u0, fmaf(hi, u1v, sp0));
                    else        sp1 = fmaf(lo, u0, fmaf(hi, u1v, sp1));
                    hrow[2 * j]     = __uint_as_float(cvt_tf32(lo));
                    hrow[2 * j + 1] = __uint_as_float(cvt_tf32(hi));
                }
            }
            psc[fh * 256 + np] = sp0;
            psc[fh * 256 + np + 128] = sp1;
        }
        __syncthreads();

        if (tw < 8) {
            // ---- heads via tf32 mma: warp tw -> nodes [tw*32, tw*32+32) ----
            const int l4 = lane >> 2, lm4 = lane & 3;
            unsigned Af[2][8][4];
            #pragma unroll
            for (int mt = 0; mt < 2; mt++) {
                const float* h0 = hsf + (tw * 32 + mt * 16 + l4) * 65;
                const float* h1r = h0 + 8 * 65;
                #pragma unroll
                for (int ks = 0; ks < 8; ks++) {
                    int cc = ks * 8 + lm4;
                    Af[mt][ks][0] = __float_as_uint(h0[cc]);
                    Af[mt][ks][1] = __float_as_uint(h1r[cc]);
                    Af[mt][ks][2] = __float_as_uint(h0[cc + 4]);
                    Af[mt][ks][3] = __float_as_uint(h1r[cc + 4]);
                }
            }
            const int n0g = base + tw * 32 + l4;
            #pragma unroll 1
            for (int nt = 0; nt < 24; nt++) {
                int f192 = nt * 8 + 2 * lm4;
                float2 bias = *(const float2*)(bb + 128 + f192);
                unsigned Bf[8][2];
                const float* bcol = atb2 + nt * 8 + l4;
                #pragma unroll
                for (int ks = 0; ks < 8; ks++) {
                    Bf[ks][0] = __float_as_uint(bcol[(ks * 8 + lm4) * 200]);
                    Bf[ks][1] = __float_as_uint(bcol[(ks * 8 + lm4 + 4) * 200]);
                }
                __nv_bfloat16* dp = (f192 < 64) ? g_kh : (f192 < 128) ? g_qh : g_vh;
                int feat = f192 & 63;
                #pragma unroll
                for (int mt = 0; mt < 2; mt++) {
                    float d0 = bias.x, d1 = bias.y, d2 = bias.x, d3 = bias.y;
                    #pragma unroll
                    for (int ks = 0; ks < 8; ks++)
                        MMA_TF32(d0, d1, d2, d3,
                                 Af[mt][ks][0], Af[mt][ks][1], Af[mt][ks][2], Af[mt][ks][3],
                                 Bf[ks][0], Bf[ks][1]);
                    int node = n0g + mt * 16;
                    if (node < NN)
                        *(unsigned*)(dp + (size_t)node * 64 + feat) = pack_bf2(d0, d1);
                    if (node + 8 < NN)
                        *(unsigned*)(dp + (size_t)(node + 8) * 64 + feat) = pack_bf2(d2, d3);
                }
            }
        } else if (tw < 12) {
            // ---- score reduce + store (128 threads, 2 nodes each) ----
            int ln = tid - 256;
            #pragma unroll
            for (int k = 0; k < 2; k++) {
                int n = ln + 128 * k;
                int node = base + n;
                if (node < NN) {
                    float s = psc[n] + psc[256 + n] + psc[512 + n] + psc[768 + n] + c1;
                    out[node] = s;
                }
            }
        }
        // warps 12-15 idle here; all warps rejoin at next tile's first sync
    }
}

// ---------------- edge kernel: 4 lanes/edge, bf16 (exact R6/R9, 50us) ----------------
__device__ __forceinline__ float sigf(float x) {
    float t;
    asm("tanh.approx.f32 %0, %1;" : "=f"(t) : "f"(x * 0.5f));
    return fmaf(t, 0.5f, 0.5f);
}
__device__ __forceinline__ float2 bf2f(unsigned u) {
    __nv_bfloat162 h = *reinterpret_cast<__nv_bfloat162*>(&u);
    return __bfloat1622float2(h);
}
__device__ __forceinline__ float edge8(uint4 kk, uint4 qq, uint4 vv) {
    float s = 0.f;
    {
        float2 kf = bf2f(kk.x), qf = bf2f(qq.x), vf = bf2f(vv.x);
        s += sigf(kf.x + qf.x) * vf.x + sigf(kf.y + qf.y) * vf.y;
    }
    {
        float2 kf = bf2f(kk.y), qf = bf2f(qq.y), vf = bf2f(vv.y);
        s += sigf(kf.x + qf.x) * vf.x + sigf(kf.y + qf.y) * vf.y;
    }
    {
        float2 kf = bf2f(kk.z), qf = bf2f(qq.z), vf = bf2f(vv.z);
        s += sigf(kf.x + qf.x) * vf.x + sigf(kf.y + qf.y) * vf.y;
    }
    {
        float2 kf = bf2f(kk.w), qf = bf2f(qq.w), vf = bf2f(vv.w);
        s += sigf(kf.x + qf.x) * vf.x + sigf(kf.y + qf.y) * vf.y;
    }
    return s;
}

__global__ __launch_bounds__(256)
void edge_kernel(const int* __restrict__ ei, float* __restrict__ out)
{
    int t = blockIdx.x * 256 + threadIdx.x;
    int e = t >> 2;
    if (e >= EE) return;
    int sub = t & 3;

    int src = ei[e];
    int dst = ei[EE + e];

    const uint4* kp = (const uint4*)(g_kh + (size_t)dst * 64 + sub * 16);
    const uint4* qp = (const uint4*)(g_qh + (size_t)src * 64 + sub * 16);
    const uint4* vp = (const uint4*)(g_vh + (size_t)src * 64 + sub * 16);
    uint4 k0 = kp[0], k1 = kp[1];
    uint4 q0 = qp[0], q1 = qp[1];
    uint4 v0 = vp[0], v1 = vp[1];

    float s = edge8(k0, q0, v0) + edge8(k1, q1, v1);

    s += __shfl_down_sync(0xffffffffu, s, 2, 4);
    s += __shfl_down_sync(0xffffffffu, s, 1, 4);
    if (sub == 0) atomicAdd(out + dst, s);
}

extern "C" void kernel_launch(void* const* d_in, const int* in_sizes, int n_in,
                              void* d_out, int out_size)
{
    const float* x      = (const float*)d_in[0];
    const int*   ei     = (const int*)d_in[1];
    const float* W1     = (const float*)d_in[2];
    const float* b1     = (const float*)d_in[3];
    const float* W2     = (const float*)d_in[4];
    const float* b2     = (const float*)d_in[5];
    const float* Wk     = (const float*)d_in[6];
    const float* bk     = (const float*)d_in[7];
    const float* Wq     = (const float*)d_in[8];
    const float* bq     = (const float*)d_in[9];
    const float* Wv     = (const float*)d_in[10];
    const float* bv     = (const float*)d_in[11];
    const float* Ws     = (const float*)d_in[12];
    const float* b_gate = (const float*)d_in[13];
    const float* Wsc    = (const float*)d_in[14];
    const float* bsc    = (const float*)d_in[15];
    float* out = (float*)d_out;

    // 8192 + 320 + 1024 + 8224 + 16640 + 12800 = 47200 floats = 184.4 KB
    size_t smemf = 47200 * sizeof(float);
    cudaFuncSetAttribute(node_fused, cudaFuncAttributeMaxDynamicSharedMemorySize, (int)smemf);

    prec<<<16, 256>>>(W2, b2, Wk, bk, Wq, bq, Wv, bv, Ws, b_gate, Wsc, bsc);
    node_fused<<<148, 512, smemf>>>(x, W1, b1, out);
    edge_kernel<<<(EE * 4) / 256, 256>>>(ei, out);
}

// round 14
// speedup vs baseline: 2.3836x; 1.2594x over previous
#include <cuda_runtime.h>
#include <cuda_bf16.h>

#define NN 100000
#define EE 1600000
#define NT 391            // node tiles of 256

#define MMA_TF32(d0,d1,d2,d3,a0,a1,a2,a3,b0,b1) \
    asm("mma.sync.aligned.m16n8k8.row.col.f32.tf32.tf32.f32 " \
        "{%0,%1,%2,%3},{%4,%5,%6,%7},{%8,%9},{%0,%1,%2,%3};" \
        : "+f"(d0), "+f"(d1), "+f"(d2), "+f"(d3) \
        : "r"(a0), "r"(a1), "r"(a2), "r"(a3), "r"(b0), "r"(b1))

__device__ __forceinline__ unsigned cvt_tf32(float f) {
    unsigned u;
    asm("cvt.rna.tf32.f32 %0, %1;" : "=r"(u) : "f"(f));
    return u;
}

// ---- device scratch (no allocation) ----
__device__ float g_Atb2[64 * 192];              // composed head weights, tf32 bits, [l][h*64+i]
__device__ float g_bh[3 * 64];                  // composed head biases (fp32)
__device__ float g_u1[64];                      // W2^T Ws^T wsc
__device__ float g_c1;
__device__ __nv_bfloat16 g_kh[(size_t)NN * 64];
__device__ __nv_bfloat16 g_qh[(size_t)NN * 64];
__device__ __nv_bfloat16 g_vh[(size_t)NN * 64];

// ---------------- prologue: compose weights (16 blocks, short chains) ----------------
__global__ __launch_bounds__(256)
void prec(const float* __restrict__ W2, const float* __restrict__ b2,
          const float* __restrict__ Wk, const float* __restrict__ bk,
          const float* __restrict__ Wq, const float* __restrict__ bq,
          const float* __restrict__ Wv, const float* __restrict__ bv,
          const float* __restrict__ Ws, const float* __restrict__ b_gate,
          const float* __restrict__ Wsc, const float* __restrict__ bsc)
{
    const int tid = threadIdx.x;
    const int blk = blockIdx.x;

    if (blk < 12) {
        const int h = blk >> 2, q = blk & 3;
        __shared__ float wht[65 * 64];
        __shared__ float w2q[16 * 64];
        __shared__ float wscs[64];
        const float* Wh = h == 0 ? Wk : h == 1 ? Wq : Wv;
        for (int idx = tid; idx < 4096; idx += 256) {
            int r = idx >> 6, c = idx & 63;
            wht[c * 65 + r] = Wh[idx];
        }
        for (int idx = tid; idx < 1024; idx += 256) {
            int j = idx >> 4, ls = idx & 15;
            w2q[idx] = W2[j * 64 + q * 16 + ls];
        }
        if (tid < 64) wscs[tid] = Wsc[tid];
        __syncthreads();

        const int i = tid & 63;
        const int lsub = tid >> 6;
        float acc[4] = {0.f, 0.f, 0.f, 0.f};
        for (int j = 0; j < 64; j++) {
            float wv = wht[j * 65 + i];
            acc[0] = fmaf(wv, w2q[j * 16 + lsub + 0],  acc[0]);
            acc[1] = fmaf(wv, w2q[j * 16 + lsub + 4],  acc[1]);
            acc[2] = fmaf(wv, w2q[j * 16 + lsub + 8],  acc[2]);
            acc[3] = fmaf(wv, w2q[j * 16 + lsub + 12], acc[3]);
        }
        float scale = (h == 2) ? wscs[i] : 1.f;
        #pragma unroll
        for (int t = 0; t < 4; t++) {
            int l = q * 16 + lsub + 4 * t;
            g_Atb2[l * 192 + h * 64 + i] = __uint_as_float(cvt_tf32(acc[t] * scale));
        }
    } else if (blk < 15) {
        const int h = blk - 12;
        __shared__ float whs[65 * 64];
        __shared__ float b2s[64], wscs[64], part[256];
        const float* Wh = h == 0 ? Wk : h == 1 ? Wq : Wv;
        for (int idx = tid; idx < 4096; idx += 256) {
            int r = idx >> 6, c = idx & 63;
            whs[c * 65 + r] = Wh[idx];
        }
        if (tid < 64) { b2s[tid] = b2[tid]; wscs[tid] = Wsc[tid]; }
        __syncthreads();
        const int i = tid & 63, jg = tid >> 6;
        float s = 0.f;
        #pragma unroll
        for (int jj = 0; jj < 16; jj++) {
            int j = jg * 16 + jj;
            s = fmaf(whs[j * 65 + i], b2s[j], s);
        }
        part[jg * 64 + i] = s;
        __syncthreads();
        if (tid < 64) {
            const float* bh_in = h == 0 ? bk : h == 1 ? bq : bv;
            float v = bh_in[tid] + part[tid] + part[64 + tid] + part[128 + tid] + part[192 + tid];
            g_bh[h * 64 + tid] = (h == 2) ? v * wscs[tid] : v;
        }
    } else {
        __shared__ float part[256], uls[64], csum[64];
        const int l = tid & 63, jg = tid >> 6;
        float s = 0.f;
        #pragma unroll
        for (int jj = 0; jj < 16; jj++) {
            int j = jg * 16 + jj;
            s = fmaf(Wsc[j], Ws[j * 64 + l], s);
        }
        part[jg * 64 + l] = s;
        __syncthreads();
        if (tid < 64) uls[tid] = part[tid] + part[64 + tid] + part[128 + tid] + part[192 + tid];
        __syncthreads();
        float t2 = 0.f;
        #pragma unroll
        for (int ll = 0; ll < 16; ll++) {
            int lv = jg * 16 + ll;
            t2 = fmaf(uls[lv], W2[lv * 64 + l], t2);
        }
        part[jg * 64 + l] = t2;
        __syncthreads();
        if (tid < 64) {
            g_u1[tid] = part[tid] + part[64 + tid] + part[128 + tid] + part[192 + tid];
            csum[tid] = fmaf(Wsc[tid], b_gate[tid], uls[tid] * b2[tid]);
        }
        __syncthreads();
        if (tid == 0) {
            float c = bsc[0];
            for (int j = 0; j < 64; j++) c += csum[j];
            g_c1 = c;
        }
    }
}

__device__ __forceinline__ unsigned pack_bf2(float a, float b) {
    __nv_bfloat162 h = __floats2bfloat162_rn(a, b);
    return *reinterpret_cast<unsigned*>(&h);
}

// ---------------- fused persistent node kernel: ALL-tf32-mma ----------------
__global__ __launch_bounds__(512, 1)
void node_fused(const float* __restrict__ x,
                const float* __restrict__ W1, const float* __restrict__ b1,
                float* __restrict__ out)
{
    extern __shared__ float sm[];
    float* w1b  = sm;                // 9216 : W1 tf32, [k=128][stride 72] (B operand)
    float* bb   = w1b + 9216;        // 320  : b1(64) | u1(64) | bh(192)
    float* atb2 = bb + 320;          // 12800: At tf32 [l=64][stride 200]
    float* xa   = atb2 + 12800;      // 17408: x tf32 [node=256][stride 68]  (half-K)
    float* hsf  = xa;                // alias: h1 tf32 [node=256][stride 65]

    const int tid = threadIdx.x;
    const int tw = tid >> 5;         // warp 0..15
    const int lane = tid & 31;
    const int l4 = lane >> 2, lm4 = lane & 3;

    // ---- stage invariants ----
    for (int idx = tid; idx < 8192; idx += 512) {
        int i = idx >> 7, k = idx & 127;
        w1b[k * 72 + i] = __uint_as_float(cvt_tf32(W1[idx]));
    }
    for (int idx = tid; idx < 12288; idx += 512)
        atb2[(idx / 192) * 200 + idx % 192] = g_Atb2[idx];
    if (tid < 64) {
        bb[tid]      = b1[tid];
        bb[64 + tid] = g_u1[tid];
    }
    if (tid < 192) bb[128 + tid] = g_bh[tid];
    const float c1 = g_c1;
    __syncthreads();

    for (int tile = blockIdx.x; tile < NT; tile += gridDim.x) {
        const int base = tile * 256;

        // ---- layer 1: tf32 mma ----
        float acc[8][4];
        #pragma unroll
        for (int nt = 0; nt < 8; nt++) {
            float2 bias = *(const float2*)(bb + nt * 8 + lm4 * 2);
            acc[nt][0] = bias.x; acc[nt][1] = bias.y;
            acc[nt][2] = bias.x; acc[nt][3] = bias.y;
        }

        #pragma unroll 1
        for (int half = 0; half < 2; half++) {
            __syncthreads();
            #pragma unroll
            for (int idx = tid; idx < 4096; idx += 512) {
                int n = idx >> 4, k4 = idx & 15;
                int nn = base + n;
                float4 v = (nn < NN) ? ((const float4*)x)[(size_t)nn * 32 + half * 16 + k4]
                                     : make_float4(0.f, 0.f, 0.f, 0.f);
                float* d = xa + n * 68 + k4 * 4;
                d[0] = __uint_as_float(cvt_tf32(v.x));
                d[1] = __uint_as_float(cvt_tf32(v.y));
                d[2] = __uint_as_float(cvt_tf32(v.z));
                d[3] = __uint_as_float(cvt_tf32(v.w));
            }
            __syncthreads();
            const float* xr = xa + (tw * 16 + l4) * 68;
            #pragma unroll
            for (int ks = 0; ks < 8; ks++) {
                int cc = ks * 8 + lm4;
                unsigned a0 = __float_as_uint(xr[cc]);
                unsigned a1 = __float_as_uint(xr[8 * 68 + cc]);
                unsigned a2 = __float_as_uint(xr[cc + 4]);
                unsigned a3 = __float_as_uint(xr[8 * 68 + cc + 4]);
                int kg = half * 64 + ks * 8 + lm4;
                const float* bcol = w1b + kg * 72;
                #pragma unroll
                for (int nt = 0; nt < 8; nt++) {
                    unsigned b0 = __float_as_uint(bcol[nt * 8 + l4]);
                    unsigned b1f = __float_as_uint(bcol[4 * 72 + nt * 8 + l4]);
                    MMA_TF32(acc[nt][0], acc[nt][1], acc[nt][2], acc[nt][3],
                             a0, a1, a2, a3, b0, b1f);
                }
            }
        }

        // ---- relu + score from fragments ----
        float sc0 = 0.f, sc1 = 0.f;
        #pragma unroll
        for (int nt = 0; nt < 8; nt++) {
            int col0 = nt * 8 + lm4 * 2;
            float u0 = bb[64 + col0], u1v = bb[64 + col0 + 1];
            acc[nt][0] = fmaxf(acc[nt][0], 0.f);
            acc[nt][1] = fmaxf(acc[nt][1], 0.f);
            acc[nt][2] = fmaxf(acc[nt][2], 0.f);
            acc[nt][3] = fmaxf(acc[nt][3], 0.f);
            sc0 = fmaf(acc[nt][0], u0, fmaf(acc[nt][1], u1v, sc0));
            sc1 = fmaf(acc[nt][2], u0, fmaf(acc[nt][3], u1v, sc1));
        }
        sc0 += __shfl_down_sync(0xffffffffu, sc0, 2, 4);
        sc0 += __shfl_down_sync(0xffffffffu, sc0, 1, 4);
        sc1 += __shfl_down_sync(0xffffffffu, sc1, 2, 4);
        sc1 += __shfl_down_sync(0xffffffffu, sc1, 1, 4);
        if (lm4 == 0) {
            int node = base + tw * 16 + l4;
            if (node < NN)     out[node]     = sc0 + c1;
            if (node + 8 < NN) out[node + 8] = sc1 + c1;
        }

        // ---- write h1 (tf32) to smem — SCALAR stores (stride 65 is odd!) ----
        __syncthreads();
        {
            float* h0 = hsf + (tw * 16 + l4) * 65;
            float* h8 = h0 + 8 * 65;
            #pragma unroll
            for (int nt = 0; nt < 8; nt++) {
                int col0 = nt * 8 + lm4 * 2;
                h0[col0]     = __uint_as_float(cvt_tf32(acc[nt][0]));
                h0[col0 + 1] = __uint_as_float(cvt_tf32(acc[nt][1]));
                h8[col0]     = __uint_as_float(cvt_tf32(acc[nt][2]));
                h8[col0 + 1] = __uint_as_float(cvt_tf32(acc[nt][3]));
            }
        }
        __syncthreads();

        // ---- heads: 16 warps = (m-pair mp, n-half nh) ----
        {
            const int mp = tw & 7, nh = tw >> 3;
            unsigned Af[2][8][4];
            #pragma unroll
            for (int mt = 0; mt < 2; mt++) {
                const float* h0 = hsf + (mp * 32 + mt * 16 + l4) * 65;
                const float* h1r = h0 + 8 * 65;
                #pragma unroll
                for (int ks = 0; ks < 8; ks++) {
                    int cc = ks * 8 + lm4;
                    Af[mt][ks][0] = __float_as_uint(h0[cc]);
                    Af[mt][ks][1] = __float_as_uint(h1r[cc]);
                    Af[mt][ks][2] = __float_as_uint(h0[cc + 4]);
                    Af[mt][ks][3] = __float_as_uint(h1r[cc + 4]);
                }
            }
            const int n0g = base + mp * 32 + l4;
            #pragma unroll 1
            for (int nt = nh * 12; nt < nh * 12 + 12; nt++) {
                int f192 = nt * 8 + 2 * lm4;
                float2 bias = *(const float2*)(bb + 128 + f192);
                unsigned Bf[8][2];
                const float* bcol = atb2 + nt * 8 + l4;
                #pragma unroll
                for (int ks = 0; ks < 8; ks++) {
                    Bf[ks][0] = __float_as_uint(bcol[(ks * 8 + lm4) * 200]);
                    Bf[ks][1] = __float_as_uint(bcol[(ks * 8 + lm4 + 4) * 200]);
                }
                __nv_bfloat16* dp = (f192 < 64) ? g_kh : (f192 < 128) ? g_qh : g_vh;
                int feat = f192 & 63;
                #pragma unroll
                for (int mt = 0; mt < 2; mt++) {
                    float d0 = bias.x, d1 = bias.y, d2 = bias.x, d3 = bias.y;
                    #pragma unroll
                    for (int ks = 0; ks < 8; ks++)
                        MMA_TF32(d0, d1, d2, d3,
                                 Af[mt][ks][0], Af[mt][ks][1], Af[mt][ks][2], Af[mt][ks][3],
                                 Bf[ks][0], Bf[ks][1]);
                    int node = n0g + mt * 16;
                    if (node < NN)
                        *(unsigned*)(dp + (size_t)node * 64 + feat) = pack_bf2(d0, d1);
                    if (node + 8 < NN)
                        *(unsigned*)(dp + (size_t)(node + 8) * 64 + feat) = pack_bf2(d2, d3);
                }
            }
        }
    }
}

// ---------------- edge kernel: 4 lanes/edge, bf16 (exact R6/R9, 50us) ----------------
__device__ __forceinline__ float sigf(float x) {
    float t;
    asm("tanh.approx.f32 %0, %1;" : "=f"(t) : "f"(x * 0.5f));
    return fmaf(t, 0.5f, 0.5f);
}
__device__ __forceinline__ float2 bf2f(unsigned u) {
    __nv_bfloat162 h = *reinterpret_cast<__nv_bfloat162*>(&u);
    return __bfloat1622float2(h);
}
__device__ __forceinline__ float edge8(uint4 kk, uint4 qq, uint4 vv) {
    float s = 0.f;
    {
        float2 kf = bf2f(kk.x), qf = bf2f(qq.x), vf = bf2f(vv.x);
        s += sigf(kf.x + qf.x) * vf.x + sigf(kf.y + qf.y) * vf.y;
    }
    {
        float2 kf = bf2f(kk.y), qf = bf2f(qq.y), vf = bf2f(vv.y);
        s += sigf(kf.x + qf.x) * vf.x + sigf(kf.y + qf.y) * vf.y;
    }
    {
        float2 kf = bf2f(kk.z), qf = bf2f(qq.z), vf = bf2f(vv.z);
        s += sigf(kf.x + qf.x) * vf.x + sigf(kf.y + qf.y) * vf.y;
    }
    {
        float2 kf = bf2f(kk.w), qf = bf2f(qq.w), vf = bf2f(vv.w);
        s += sigf(kf.x + qf.x) * vf.x + sigf(kf.y + qf.y) * vf.y;
    }
    return s;
}

__global__ __launch_bounds__(256)
void edge_kernel(const int* __restrict__ ei, float* __restrict__ out)
{
    int t = blockIdx.x * 256 + threadIdx.x;
    int e = t >> 2;
    if (e >= EE) return;
    int sub = t & 3;

    int src = ei[e];
    int dst = ei[EE + e];

    const uint4* kp = (const uint4*)(g_kh + (size_t)dst * 64 + sub * 16);
    const uint4* qp = (const uint4*)(g_qh + (size_t)src * 64 + sub * 16);
    const uint4* vp = (const uint4*)(g_vh + (size_t)src * 64 + sub * 16);
    uint4 k0 = kp[0], k1 = kp[1];
    uint4 q0 = qp[0], q1 = qp[1];
    uint4 v0 = vp[0], v1 = vp[1];

    float s = edge8(k0, q0, v0) + edge8(k1, q1, v1);

    s += __shfl_down_sync(0xffffffffu, s, 2, 4);
    s += __shfl_down_sync(0xffffffffu, s, 1, 4);
    if (sub == 0) atomicAdd(out + dst, s);
}

extern "C" void kernel_launch(void* const* d_in, const int* in_sizes, int n_in,
                              void* d_out, int out_size)
{
    const float* x      = (const float*)d_in[0];
    const int*   ei     = (const int*)d_in[1];
    const float* W1     = (const float*)d_in[2];
    const float* b1     = (const float*)d_in[3];
    const float* W2     = (const float*)d_in[4];
    const float* b2     = (const float*)d_in[5];
    const float* Wk     = (const float*)d_in[6];
    const float* bk     = (const float*)d_in[7];
    const float* Wq     = (const float*)d_in[8];
    const float* bq     = (const float*)d_in[9];
    const float* Wv     = (const float*)d_in[10];
    const float* bv     = (const float*)d_in[11];
    const float* Ws     = (const float*)d_in[12];
    const float* b_gate = (const float*)d_in[13];
    const float* Wsc    = (const float*)d_in[14];
    const float* bsc    = (const float*)d_in[15];
    float* out = (float*)d_out;

    // 9216 + 320 + 12800 + 17408 = 39744 floats = 155.3 KB
    size_t smemf = 39744 * sizeof(float);
    cudaFuncSetAttribute(node_fused, cudaFuncAttributeMaxDynamicSharedMemorySize, (int)smemf);

    prec<<<16, 256>>>(W2, b2, Wk, bk, Wq, bq, Wv, bv, Ws, b_gate, Wsc, bsc);
    node_fused<<<148, 512, smemf>>>(x, W1, b1, out);
    edge_kernel<<<(EE * 4) / 256, 256>>>(ei, out);
}